// round 4
// baseline (speedup 1.0000x reference)
#include <cuda_runtime.h>

// Problem constants
#define NB     32
#define TT     4096
#define ENC_H  512
#define ATT_H  256
#define OUTD   80
#define SPK    64
#define KW     31
#define NWMAX  19
#define GRID   256

// Device scratch (no allocations allowed)
__device__ unsigned bar_cnt = 0;
__device__ unsigned bar_gen = 0;                     // monotonic across replays
__device__ float    d_argval[NB][8];
__device__ int      d_argidx[NB][8];
__device__ int      d_lo[NB];
__device__ int      d_nwin[NB];
__device__ unsigned d_count[NB];
__device__ float    d_bias0[NB][ATT_H];              // softsign(spkr@W_spkr)+speed*W_speed
__device__ float    d_h[1024][NB];                   // prenet layer-1, k-major
__device__ float    d_p2part[8][NB][512];            // prenet layer-2 split-K partials
__device__ float    d_logit_part[NB][NWMAX][8];

// grid-wide sense barrier (all GRID blocks co-resident by construction)
__device__ __forceinline__ void grid_sync()
{
    __syncthreads();
    if (threadIdx.x == 0) {
        volatile unsigned* vg = &bar_gen;
        unsigned gen = *vg;                 // read BEFORE arriving
        __threadfence();
        if (atomicAdd(&bar_cnt, 1u) == GRID - 1) {
            bar_cnt = 0;
            __threadfence();
            atomicAdd(&bar_gen, 1u);        // release
        } else {
            while (*vg == gen) { __nanosleep(32); }
        }
        __threadfence();                    // acquire
    }
    __syncthreads();
}

union SmemU {
    struct {                                // phase A
        float rv[128]; int ri[128];
        float dec_s[32][145];               // 145 mod 32 = 17, conflict-free
        float w_s[144][4];
    } a;
    struct {                                // phase B (prenet2)
        float h_s[128][33];
        float wt[128][36];
    } b;
    struct {                                // phase C (window)
        float p_s[512];
        float enc_t[NWMAX][132];
        float red_s[NWMAX][8][33];
        float pa_s[NWMAX + 30 + 3];
        float convw_s[32 * KW];
        float bias_s[32], benc_s[32], wproj_s[32];
    } c;
};

__global__ __launch_bounds__(256) void k_fused(
    const float* __restrict__ input_enc,    // [N,T,512]
    const float* __restrict__ input_dec,    // [N,1,80]
    const float* __restrict__ prev_att,     // [N,T,1]
    const float* __restrict__ spkr,         // [N,1,64]
    const int*   __restrict__ lengths,      // [N]
    const float* __restrict__ speed,        // [N]
    const float* __restrict__ W_enc,        // [512,256]
    const float* __restrict__ b_enc,        // [256]
    const float* __restrict__ W_spkr,       // [64,256]
    const float* __restrict__ conv_w,       // [256,1,31]
    const float* __restrict__ W_dec,        // [512,256]
    const float* __restrict__ W_speed,      // [1,256]
    const float* __restrict__ Wp1,          // [144,1024]
    const float* __restrict__ bp1,          // [1024]
    const float* __restrict__ Wp2,          // [1024,512]
    const float* __restrict__ bp2,          // [512]
    const float* __restrict__ W_proj,       // [256,1]
    float* __restrict__ out)                // [N,T,1]
{
    __shared__ SmemU sm;
    __shared__ int last_s;
    const int tid = threadIdx.x;
    const int blk = blockIdx.x;

    // ============================ PHASE A ============================
    {
        const int b = blk >> 3;
        const int j = blk & 7;

        // zero output chunk: 512 floats = 128 float4
        if (tid < 128) {
            ((float4*)(out + (size_t)b * TT + j * 512))[tid] =
                make_float4(0.f, 0.f, 0.f, 0.f);
        }

        // argmax partial over chunk [j*512, j*512+512), first max wins
        if (tid < 128) {
            const float4* pa4 = (const float4*)(prev_att + (size_t)b * TT + j * 512);
            float4 v = pa4[tid];
            float bv = v.x; int bi = 0;
            if (v.y > bv) { bv = v.y; bi = 1; }
            if (v.z > bv) { bv = v.z; bi = 2; }
            if (v.w > bv) { bv = v.w; bi = 3; }
            sm.a.rv[tid] = bv;
            sm.a.ri[tid] = j * 512 + tid * 4 + bi;
        }

        // L2 prefetch slice of W_enc (512KB / 256 blocks = 128 float4)
        float pf = 0.f;
        if (tid < 128) {
            float4 w = __ldcg(&((const float4*)W_enc)[blk * 128 + tid]);
            pf = w.x + w.y + w.z + w.w;
        }
        asm volatile("" :: "f"(pf));        // defeat DCE

        // prenet1 staging: dec_s (all 32 batches) + this block's 4 Wp1 columns
        const int cbase = blk * 4;
        for (int i = tid; i < NB * OUTD; i += 256) {
            int b2 = i / OUTD, k = i - b2 * OUTD;
            sm.a.dec_s[b2][k] = input_dec[i];
        }
        for (int i = tid; i < NB * SPK; i += 256) {
            int b2 = i >> 6, k = i & 63;
            sm.a.dec_s[b2][OUTD + k] = spkr[i];
        }
        for (int i = tid; i < 144; i += 256)
            *(float4*)&sm.a.w_s[i][0] = *(const float4*)&Wp1[i * 1024 + cbase];
        __syncthreads();

        // argmax reduce 128 -> 1
        for (int s = 64; s > 0; s >>= 1) {
            if (tid < s) {
                float ov = sm.a.rv[tid + s]; int oi = sm.a.ri[tid + s];
                if (ov > sm.a.rv[tid] || (ov == sm.a.rv[tid] && oi < sm.a.ri[tid])) {
                    sm.a.rv[tid] = ov; sm.a.ri[tid] = oi;
                }
            }
            __syncthreads();
        }
        if (tid == 0) { d_argval[b][j] = sm.a.rv[0]; d_argidx[b][j] = sm.a.ri[0]; }

        // prenet1: tid -> (bb = tid>>3, cc = (tid>>1)&3, ss = tid&1), 72 k each
        {
            const int bb = tid >> 3, cc = (tid >> 1) & 3, ss = tid & 1;
            float acc = 0.f;
            #pragma unroll 8
            for (int k = ss * 72; k < ss * 72 + 72; k++)
                acc = fmaf(sm.a.dec_s[bb][k], sm.a.w_s[k][cc], acc);
            acc += __shfl_xor_sync(0xffffffffu, acc, 1);
            if (ss == 0)
                d_h[cbase + cc][bb] = fmaxf(acc + bp1[cbase + cc], 0.f);
        }

        // j==0 block: spkr softsign + speed bias, counter reset
        if (j == 0) {
            if (tid == 0) d_count[b] = 0u;
            float sa = 0.f;
            #pragma unroll 8
            for (int k = 0; k < SPK; k++)
                sa = fmaf(spkr[b * SPK + k], W_spkr[k * ATT_H + tid], sa);
            float v = sa / (1.f + fabsf(sa));
            d_bias0[b][tid] = fmaf(speed[b], W_speed[tid], v);
        }
    }

    grid_sync();

    // ============================ PHASE B ============================
    if (blk < 128) {
        // prenet2 split-K: cb = (blk&15)*32, ks = blk>>4
        const int cb = (blk & 15) * 32;
        const int k0 = (blk >> 4) * 128;
        const int b = tid & 31;
        const int s = tid >> 5;

        for (int i = tid; i < 32 * 128; i += 256) {
            int kk = i >> 5, b2 = i & 31;
            sm.b.h_s[kk][b2] = d_h[k0 + kk][b2];
        }
        for (int i = tid; i < 128 * 32; i += 256) {
            int kk = i >> 5, sc = i & 31;
            sm.b.wt[kk][sc] = Wp2[(k0 + kk) * 512 + cb + sc];
        }
        __syncthreads();

        float4 acc = make_float4(0.f, 0.f, 0.f, 0.f);
        #pragma unroll 8
        for (int kk = 0; kk < 128; kk++) {
            float hv = sm.b.h_s[kk][b];
            float4 w = *(const float4*)&sm.b.wt[kk][s * 4];
            acc.x = fmaf(hv, w.x, acc.x);
            acc.y = fmaf(hv, w.y, acc.y);
            acc.z = fmaf(hv, w.z, acc.z);
            acc.w = fmaf(hv, w.w, acc.w);
        }
        *(float4*)&d_p2part[blk >> 4][b][cb + s * 4] = acc;
    } else if (blk < 160) {
        // argmax combine for batch b
        const int b = blk - 128;
        if (tid == 0) {
            float bv = d_argval[b][0]; int bi = d_argidx[b][0];
            #pragma unroll
            for (int j = 1; j < 8; j++) {
                float v = d_argval[b][j];
                if (v > bv) { bv = v; bi = d_argidx[b][j]; }
            }
            int lo = max(bi - 9, 0);
            int hi = min(bi + 9, lengths[b] - 1);
            d_lo[b]   = lo;
            d_nwin[b] = hi - lo + 1;
        }
    } else {
        // prefetch enc window rows into L2 (3 blocks per batch)
        const int i = blk - 160;           // 0..95
        const int b = i & 31;
        const int part = i >> 5;           // 0..2
        // recombine argmax locally (cheap, no dependence on blocks 128-159)
        float bv = d_argval[b][0]; int bi = d_argidx[b][0];
        #pragma unroll
        for (int j = 1; j < 8; j++) {
            float v = d_argval[b][j];
            if (v > bv) { bv = v; bi = d_argidx[b][j]; }
        }
        const int lo = max(bi - 9, 0);
        const float4* enc4 = (const float4*)(input_enc + (size_t)b * TT * ENC_H);
        float pf = 0.f;
        const int r0 = part * 7;
        const int r1 = min(r0 + 7, NWMAX);
        if (tid < 128) {
            for (int r = r0; r < r1; r++) {
                int row = lo + r; if (row > TT - 1) row = TT - 1;
                float4 v = __ldcg(&enc4[(size_t)row * (ENC_H / 4) + tid]);
                pf += v.x + v.y + v.z + v.w;
            }
        }
        asm volatile("" :: "f"(pf));
    }

    grid_sync();

    // ============================ PHASE C ============================
    {
        const int b  = blk >> 3;
        const int cg = blk & 7;
        const int c0 = cg * 32;

        const int lo   = d_lo[b];
        const int nwin = d_nwin[b];

        // reconstruct pout = relu(bp2 + sum split-K partials)
        #pragma unroll
        for (int r = 0; r < 2; r++) {
            int k = tid + r * 256;
            float v = bp2[k];
            #pragma unroll
            for (int j = 0; j < 8; j++) v += d_p2part[j][b][k];
            sm.c.p_s[k] = fmaxf(v, 0.f);
        }
        for (int i = tid; i < nwin + 30; i += 256) {
            int p = lo - 15 + i;
            sm.c.pa_s[i] = (p >= 0 && p < TT) ? prev_att[(size_t)b * TT + p] : 0.f;
        }
        for (int i = tid; i < 32 * KW; i += 256) sm.c.convw_s[i] = conv_w[c0 * KW + i];
        if (tid < 32) {
            sm.c.benc_s[tid]  = b_enc[c0 + tid];
            sm.c.wproj_s[tid] = W_proj[c0 + tid];
        }
        __syncthreads();

        // bias slice: pout @ W_dec[:, c0..c0+32) + bias0
        {
            const int cl = tid & 31, kq = tid >> 5;
            float acc = 0.f;
            #pragma unroll 8
            for (int j = 0; j < 64; j++) {
                int k = kq * 64 + j;
                acc = fmaf(sm.c.p_s[k], W_dec[k * ATT_H + c0 + cl], acc);
            }
            sm.c.red_s[0][kq][cl] = acc;
        }
        __syncthreads();
        if (tid < 32) {
            float s = d_bias0[b][c0 + tid];
            #pragma unroll
            for (int q = 0; q < 8; q++) s += sm.c.red_s[0][q][tid];
            sm.c.bias_s[tid] = s;
        }

        // enc matvec
        const int cl  = tid & 15;
        const int kq  = tid >> 4;
        const int ca  = c0 + cl;
        const int cb2 = c0 + cl + 16;

        float acc_a[NWMAX], acc_b[NWMAX];
        #pragma unroll
        for (int t = 0; t < NWMAX; t++) { acc_a[t] = 0.f; acc_b[t] = 0.f; }

        const float4* enc4 = (const float4*)(input_enc + (size_t)b * TT * ENC_H);

        for (int tile = 0; tile < 4; tile++) {
            __syncthreads();
            for (int i = tid; i < NWMAX * 32; i += 256) {
                int t = i >> 5, q = i & 31;
                int row = lo + t; if (row > TT - 1) row = TT - 1;
                float4 e = enc4[(size_t)row * (ENC_H / 4) + tile * 32 + q];
                *(float4*)&sm.c.enc_t[t][q * 4] = e;
            }
            __syncthreads();

            #pragma unroll
            for (int k4 = 0; k4 < 2; k4++) {
                const int kk = kq * 8 + k4 * 4;
                const int kg = tile * 128 + kk;
                float4 wa, wb;
                wa.x = W_enc[(kg + 0) * ATT_H + ca];
                wa.y = W_enc[(kg + 1) * ATT_H + ca];
                wa.z = W_enc[(kg + 2) * ATT_H + ca];
                wa.w = W_enc[(kg + 3) * ATT_H + ca];
                wb.x = W_enc[(kg + 0) * ATT_H + cb2];
                wb.y = W_enc[(kg + 1) * ATT_H + cb2];
                wb.z = W_enc[(kg + 2) * ATT_H + cb2];
                wb.w = W_enc[(kg + 3) * ATT_H + cb2];
                #pragma unroll
                for (int t = 0; t < NWMAX; t++) {
                    float4 e = *(const float4*)&sm.c.enc_t[t][kk];
                    acc_a[t] = fmaf(e.x, wa.x, acc_a[t]);
                    acc_a[t] = fmaf(e.y, wa.y, acc_a[t]);
                    acc_a[t] = fmaf(e.z, wa.z, acc_a[t]);
                    acc_a[t] = fmaf(e.w, wa.w, acc_a[t]);
                    acc_b[t] = fmaf(e.x, wb.x, acc_b[t]);
                    acc_b[t] = fmaf(e.y, wb.y, acc_b[t]);
                    acc_b[t] = fmaf(e.z, wb.z, acc_b[t]);
                    acc_b[t] = fmaf(e.w, wb.w, acc_b[t]);
                }
            }
        }

        // combine kq halves within warps, stash per-warp partials
        const int w = tid >> 5;
        #pragma unroll
        for (int t = 0; t < NWMAX; t++) {
            float va = acc_a[t] + __shfl_xor_sync(0xffffffffu, acc_a[t], 16);
            float vb = acc_b[t] + __shfl_xor_sync(0xffffffffu, acc_b[t], 16);
            if ((tid & 31) < 16) {
                sm.c.red_s[t][w][cl]      = va;
                sm.c.red_s[t][w][cl + 16] = vb;
            }
        }
        __syncthreads();

        // parallel tail
        const int c2 = tid & 31;
        const int tq = tid >> 5;
        #pragma unroll
        for (int p = 0; p < 3; p++) {
            const int t = p * 8 + tq;
            float v = 0.f;
            if (t < nwin) {
                float s = 0.f;
                #pragma unroll
                for (int q = 0; q < 8; q++) s += sm.c.red_s[t][q][c2];
                s += sm.c.benc_s[c2];
                s = s / (1.f + fabsf(s));
                s += sm.c.bias_s[c2];
                float cv = 0.f;
                #pragma unroll
                for (int j = 0; j < KW; j++)
                    cv = fmaf(sm.c.pa_s[t + j], sm.c.convw_s[c2 * KW + j], cv);
                s += cv;
                v = tanhf(s) * sm.c.wproj_s[c2];
            }
            #pragma unroll
            for (int o = 16; o > 0; o >>= 1) v += __shfl_down_sync(0xffffffffu, v, o);
            if (c2 == 0 && t < nwin) d_logit_part[b][t][cg] = v;
        }

        // last-block-done fused softmax
        __threadfence();
        __syncthreads();
        if (tid == 0) {
            unsigned old = atomicAdd(&d_count[b], 1u);
            last_s = (old == 7u) ? 1 : 0;
        }
        __syncthreads();
        if (last_s && tid < 32) {
            const int t = tid;
            float lg = -1e30f;
            if (t < nwin) {
                float s = 0.f;
                #pragma unroll
                for (int q = 0; q < 8; q++) s += __ldcg(&d_logit_part[b][t][q]);
                lg = s;
            }
            float m = lg;
            #pragma unroll
            for (int o = 16; o > 0; o >>= 1) m = fmaxf(m, __shfl_xor_sync(0xffffffffu, m, o));
            float e = (t < nwin) ? expf(lg - m) : 0.f;
            float sum = e;
            #pragma unroll
            for (int o = 16; o > 0; o >>= 1) sum += __shfl_xor_sync(0xffffffffu, sum, o);
            if (t < nwin) out[(size_t)b * TT + lo + t] = e / sum;
        }
    }
}

// ---------------------------------------------------------------------------
extern "C" void kernel_launch(void* const* d_in, const int* in_sizes, int n_in,
                              void* d_out, int out_size)
{
    const float* input_enc = (const float*)d_in[0];
    const float* input_dec = (const float*)d_in[1];
    const float* prev_att  = (const float*)d_in[2];
    const float* spkr      = (const float*)d_in[3];
    const int*   lengths   = (const int*)  d_in[4];
    const float* speed     = (const float*)d_in[5];
    const float* W_enc     = (const float*)d_in[6];
    const float* b_enc     = (const float*)d_in[7];
    const float* W_spkr    = (const float*)d_in[8];
    const float* conv_w    = (const float*)d_in[9];
    const float* W_dec     = (const float*)d_in[10];
    const float* W_speed   = (const float*)d_in[11];
    const float* Wp1       = (const float*)d_in[12];
    const float* bp1       = (const float*)d_in[13];
    const float* Wp2       = (const float*)d_in[14];
    const float* bp2       = (const float*)d_in[15];
    const float* W_proj    = (const float*)d_in[16];
    // d_in[17] = b_proj: constant shift, cancels in the masked softmax.

    k_fused<<<GRID, 256>>>(input_enc, input_dec, prev_att, spkr, lengths, speed,
                           W_enc, b_enc, W_spkr, conv_w, W_dec, W_speed,
                           Wp1, bp1, Wp2, bp2, W_proj, (float*)d_out);
}

// round 5
// speedup vs baseline: 1.1464x; 1.1464x over previous
#include <cuda_runtime.h>

// Problem constants
#define NB     32
#define TT     4096
#define ENC_H  512
#define ATT_H  256
#define OUTD   80
#define SPK    64
#define KW     31
#define NWMAX  19
#define GRID   256

// Device scratch (no allocations allowed)
__device__ unsigned bar_cnt = 0;
__device__ unsigned bar_gen = 0;                 // monotonic across replays
__device__ unsigned d_cnt2  = 0;                 // prenet2 producer counter
__device__ float    d_argval[NB][8];
__device__ int      d_argidx[NB][8];
__device__ unsigned d_count[NB];
__device__ float    d_bias0[NB][ATT_H];
__device__ float    d_h[1024][NB];               // prenet layer-1, k-major
__device__ float    d_p2part[16][NB][512];       // prenet layer-2 split-K partials
__device__ float    d_logit_part[NB][NWMAX][8];

// grid-wide sense barrier (all GRID blocks co-resident: 2 blocks/SM by regs/smem)
__device__ __forceinline__ void grid_sync()
{
    __syncthreads();
    if (threadIdx.x == 0) {
        volatile unsigned* vg = &bar_gen;
        unsigned gen = *vg;
        __threadfence();
        if (atomicAdd(&bar_cnt, 1u) == GRID - 1) {
            bar_cnt = 0;
            __threadfence();
            atomicAdd(&bar_gen, 1u);
        } else {
            while (*vg == gen) { __nanosleep(32); }
        }
        __threadfence();
    }
    __syncthreads();
}

union SmemU {
    struct {                                // phase A
        float rv[128]; int ri[128];
        float dec_s[32][145];
        float w_s[144][4];
    } a;
    struct {                                // prenet2 (64-k slice)
        float h_s[64][33];
        float wt[64][36];
    } b;
    struct {                                // window
        float p_s[512];
        float enc_t[NWMAX][132];
        float red_s[NWMAX][8][33];
        float bias_red[8][33];
        float pa_s[NWMAX + 30 + 3];
        float convw_s[32 * KW];
        float bias_s[32], benc_s[32], wproj_s[32];
    } c;
};

__global__ __launch_bounds__(256) void k_fused(
    const float* __restrict__ input_enc,
    const float* __restrict__ input_dec,
    const float* __restrict__ prev_att,
    const float* __restrict__ spkr,
    const int*   __restrict__ lengths,
    const float* __restrict__ speed,
    const float* __restrict__ W_enc,
    const float* __restrict__ b_enc,
    const float* __restrict__ W_spkr,
    const float* __restrict__ conv_w,
    const float* __restrict__ W_dec,
    const float* __restrict__ W_speed,
    const float* __restrict__ Wp1,
    const float* __restrict__ bp1,
    const float* __restrict__ Wp2,
    const float* __restrict__ bp2,
    const float* __restrict__ W_proj,
    float* __restrict__ out)
{
    __shared__ SmemU sm;
    __shared__ int last_s, sh_lo, sh_nwin;
    const int tid = threadIdx.x;
    const int blk = blockIdx.x;
    const int b  = blk >> 3;                // batch for argmax/zero/window
    const int cg = blk & 7;                 // channel group for window

    // ============================ PHASE A ============================
    {
        // counter resets (before grid_sync; all increments happen after it)
        if (blk == 0 && tid == 0) d_cnt2 = 0u;
        if (cg == 0 && tid == 0) d_count[b] = 0u;

        // zero output chunk: 512 floats
        if (tid < 128) {
            ((float4*)(out + (size_t)b * TT + cg * 512))[tid] =
                make_float4(0.f, 0.f, 0.f, 0.f);
        }

        // argmax partial over chunk [cg*512, cg*512+512), first max wins
        if (tid < 128) {
            const float4* pa4 = (const float4*)(prev_att + (size_t)b * TT + cg * 512);
            float4 v = pa4[tid];
            float bv = v.x; int bi = 0;
            if (v.y > bv) { bv = v.y; bi = 1; }
            if (v.z > bv) { bv = v.z; bi = 2; }
            if (v.w > bv) { bv = v.w; bi = 3; }
            sm.a.rv[tid] = bv;
            sm.a.ri[tid] = cg * 512 + tid * 4 + bi;
        }

        // prenet1 staging
        const int cbase = blk * 4;
        for (int i = tid; i < NB * OUTD; i += 256) {
            int b2 = i / OUTD, k = i - b2 * OUTD;
            sm.a.dec_s[b2][k] = input_dec[i];
        }
        for (int i = tid; i < NB * SPK; i += 256) {
            int b2 = i >> 6, k = i & 63;
            sm.a.dec_s[b2][OUTD + k] = spkr[i];
        }
        for (int i = tid; i < 144; i += 256)
            *(float4*)&sm.a.w_s[i][0] = *(const float4*)&Wp1[i * 1024 + cbase];
        __syncthreads();

        // argmax reduce 128 -> 1
        for (int s = 64; s > 0; s >>= 1) {
            if (tid < s) {
                float ov = sm.a.rv[tid + s]; int oi = sm.a.ri[tid + s];
                if (ov > sm.a.rv[tid] || (ov == sm.a.rv[tid] && oi < sm.a.ri[tid])) {
                    sm.a.rv[tid] = ov; sm.a.ri[tid] = oi;
                }
            }
            __syncthreads();
        }
        if (tid == 0) { d_argval[b][cg] = sm.a.rv[0]; d_argidx[b][cg] = sm.a.ri[0]; }

        // prenet1: 4 channels x 32 batches, 2 threads split k
        {
            const int bb = tid >> 3, cc = (tid >> 1) & 3, ss = tid & 1;
            float acc = 0.f;
            #pragma unroll 8
            for (int k = ss * 72; k < ss * 72 + 72; k++)
                acc = fmaf(sm.a.dec_s[bb][k], sm.a.w_s[k][cc], acc);
            acc += __shfl_xor_sync(0xffffffffu, acc, 1);
            if (ss == 0)
                d_h[cbase + cc][bb] = fmaxf(acc + bp1[cbase + cc], 0.f);
        }

        // cg==0 block: spkr softsign + speed bias
        if (cg == 0) {
            float sa = 0.f;
            #pragma unroll 8
            for (int k = 0; k < SPK; k++)
                sa = fmaf(spkr[b * SPK + k], W_spkr[k * ATT_H + tid], sa);
            float v = sa / (1.f + fabsf(sa));
            d_bias0[b][tid] = fmaf(speed[b], W_speed[tid], v);
        }
    }

    grid_sync();

    // ============================ PHASE B: prenet2 slice (all 256 blocks) ====
    {
        const int cb = (blk & 15) * 32;     // 16 channel groups of Wp2 output
        const int ks = blk >> 4;            // 16 k-splits of 64
        const int k0 = ks * 64;
        const int bb = tid & 31;
        const int s  = tid >> 5;

        for (int i = tid; i < 32 * 64; i += 256) {
            int kk = i >> 5, b2 = i & 31;
            sm.b.h_s[kk][b2] = d_h[k0 + kk][b2];
        }
        for (int i = tid; i < 64 * 32; i += 256) {
            int kk = i >> 5, sc = i & 31;
            sm.b.wt[kk][sc] = Wp2[(k0 + kk) * 512 + cb + sc];
        }
        __syncthreads();

        float4 acc = make_float4(0.f, 0.f, 0.f, 0.f);
        #pragma unroll 8
        for (int kk = 0; kk < 64; kk++) {
            float hv = sm.b.h_s[kk][bb];
            float4 w = *(const float4*)&sm.b.wt[kk][s * 4];
            acc.x = fmaf(hv, w.x, acc.x);
            acc.y = fmaf(hv, w.y, acc.y);
            acc.z = fmaf(hv, w.z, acc.z);
            acc.w = fmaf(hv, w.w, acc.w);
        }
        *(float4*)&d_p2part[ks][bb][cb + s * 4] = acc;

        __threadfence();
        __syncthreads();                    // all stores done before counting
        if (tid == 0) atomicAdd(&d_cnt2, 1u);
    }
    __syncthreads();                        // smem union switch b -> c

    // ============================ PHASE C: window ============================
    {
        const int c0 = cg * 32;

        // combine argmax -> lo, nwin
        if (tid == 0) {
            float bv = d_argval[b][0]; int bi = d_argidx[b][0];
            #pragma unroll
            for (int j = 1; j < 8; j++) {
                float v = d_argval[b][j];
                if (v > bv) { bv = v; bi = d_argidx[b][j]; }
            }
            int lo = max(bi - 9, 0);
            int hi = min(bi + 9, lengths[b] - 1);
            sh_lo = lo;
            sh_nwin = hi - lo + 1;
        }
        __syncthreads();
        const int lo   = sh_lo;
        const int nwin = sh_nwin;

        // small staging
        for (int i = tid; i < nwin + 30; i += 256) {
            int p = lo - 15 + i;
            sm.c.pa_s[i] = (p >= 0 && p < TT) ? prev_att[(size_t)b * TT + p] : 0.f;
        }
        for (int i = tid; i < 32 * KW; i += 256) sm.c.convw_s[i] = conv_w[c0 * KW + i];
        if (tid < 32) {
            sm.c.benc_s[tid]  = b_enc[c0 + tid];
            sm.c.wproj_s[tid] = W_proj[c0 + tid];
        }

        // enc matvec: cl = tid&15 -> channels c0+cl, c0+cl+16; kq = tid>>4
        const int cl  = tid & 15;
        const int kq  = tid >> 4;
        const int ca  = c0 + cl;
        const int cb2 = c0 + cl + 16;

        float acc_a[NWMAX], acc_b[NWMAX];
        #pragma unroll
        for (int t = 0; t < NWMAX; t++) { acc_a[t] = 0.f; acc_b[t] = 0.f; }

        const float4* enc4 = (const float4*)(input_enc + (size_t)b * TT * ENC_H);

        for (int tile = 0; tile < 4; tile++) {
            __syncthreads();
            for (int i = tid; i < NWMAX * 32; i += 256) {
                int t = i >> 5, q = i & 31;
                int row = lo + t; if (row > TT - 1) row = TT - 1;
                float4 e = enc4[(size_t)row * (ENC_H / 4) + tile * 32 + q];
                *(float4*)&sm.c.enc_t[t][q * 4] = e;
            }
            __syncthreads();

            #pragma unroll
            for (int k4 = 0; k4 < 2; k4++) {
                const int kk = kq * 8 + k4 * 4;
                const int kg = tile * 128 + kk;
                float4 wa, wb;
                wa.x = W_enc[(kg + 0) * ATT_H + ca];
                wa.y = W_enc[(kg + 1) * ATT_H + ca];
                wa.z = W_enc[(kg + 2) * ATT_H + ca];
                wa.w = W_enc[(kg + 3) * ATT_H + ca];
                wb.x = W_enc[(kg + 0) * ATT_H + cb2];
                wb.y = W_enc[(kg + 1) * ATT_H + cb2];
                wb.z = W_enc[(kg + 2) * ATT_H + cb2];
                wb.w = W_enc[(kg + 3) * ATT_H + cb2];
                #pragma unroll
                for (int t = 0; t < NWMAX; t++) {
                    float4 e = *(const float4*)&sm.c.enc_t[t][kk];
                    acc_a[t] = fmaf(e.x, wa.x, acc_a[t]);
                    acc_a[t] = fmaf(e.y, wa.y, acc_a[t]);
                    acc_a[t] = fmaf(e.z, wa.z, acc_a[t]);
                    acc_a[t] = fmaf(e.w, wa.w, acc_a[t]);
                    acc_b[t] = fmaf(e.x, wb.x, acc_b[t]);
                    acc_b[t] = fmaf(e.y, wb.y, acc_b[t]);
                    acc_b[t] = fmaf(e.z, wb.z, acc_b[t]);
                    acc_b[t] = fmaf(e.w, wb.w, acc_b[t]);
                }
            }
        }

        // stash per-warp matvec partials
        const int w = tid >> 5;
        #pragma unroll
        for (int t = 0; t < NWMAX; t++) {
            float va = acc_a[t] + __shfl_xor_sync(0xffffffffu, acc_a[t], 16);
            float vb = acc_b[t] + __shfl_xor_sync(0xffffffffu, acc_b[t], 16);
            if ((tid & 31) < 16) {
                sm.c.red_s[t][w][cl]      = va;
                sm.c.red_s[t][w][cl + 16] = vb;
            }
        }

        // wait for prenet2 producers (long since done: overlapped with matvec)
        if (tid == 0) {
            volatile unsigned* vc = &d_cnt2;
            while (*vc < GRID) { }
        }
        __syncthreads();
        __threadfence();

        // reconstruct pout = relu(bp2 + sum of 16 split-K partials)
        #pragma unroll
        for (int r = 0; r < 2; r++) {
            int k = tid + r * 256;
            float v = bp2[k];
            #pragma unroll
            for (int j = 0; j < 16; j++) v += __ldcg(&d_p2part[j][b][k]);
            sm.c.p_s[k] = fmaxf(v, 0.f);
        }
        __syncthreads();

        // bias slice: pout @ W_dec[:, c0..c0+32) + bias0
        {
            const int cl2 = tid & 31, kq2 = tid >> 5;
            float acc = 0.f;
            #pragma unroll 8
            for (int j = 0; j < 64; j++) {
                int k = kq2 * 64 + j;
                acc = fmaf(sm.c.p_s[k], W_dec[k * ATT_H + c0 + cl2], acc);
            }
            sm.c.bias_red[kq2][cl2] = acc;
        }
        __syncthreads();
        if (tid < 32) {
            float s = d_bias0[b][c0 + tid];
            #pragma unroll
            for (int q = 0; q < 8; q++) s += sm.c.bias_red[q][tid];
            sm.c.bias_s[tid] = s;
        }
        __syncthreads();

        // parallel tail: warp tq handles t = p*8 + tq
        const int c2 = tid & 31;
        const int tq = tid >> 5;
        #pragma unroll
        for (int p = 0; p < 3; p++) {
            const int t = p * 8 + tq;
            float v = 0.f;
            if (t < nwin) {
                float s = 0.f;
                #pragma unroll
                for (int q = 0; q < 8; q++) s += sm.c.red_s[t][q][c2];
                s += sm.c.benc_s[c2];
                s = s / (1.f + fabsf(s));
                s += sm.c.bias_s[c2];
                float cv = 0.f;
                #pragma unroll
                for (int j = 0; j < KW; j++)
                    cv = fmaf(sm.c.pa_s[t + j], sm.c.convw_s[c2 * KW + j], cv);
                s += cv;
                v = tanhf(s) * sm.c.wproj_s[c2];
            }
            #pragma unroll
            for (int o = 16; o > 0; o >>= 1) v += __shfl_down_sync(0xffffffffu, v, o);
            if (c2 == 0 && t < nwin) d_logit_part[b][t][cg] = v;
        }

        // last-block-done fused softmax
        __threadfence();
        __syncthreads();
        if (tid == 0) {
            unsigned old = atomicAdd(&d_count[b], 1u);
            last_s = (old == 7u) ? 1 : 0;
        }
        __syncthreads();
        if (last_s && tid < 32) {
            const int t = tid;
            float lg = -1e30f;
            if (t < nwin) {
                float s = 0.f;
                #pragma unroll
                for (int q = 0; q < 8; q++) s += __ldcg(&d_logit_part[b][t][q]);
                lg = s;
            }
            float m = lg;
            #pragma unroll
            for (int o = 16; o > 0; o >>= 1) m = fmaxf(m, __shfl_xor_sync(0xffffffffu, m, o));
            float e = (t < nwin) ? expf(lg - m) : 0.f;
            float sum = e;
            #pragma unroll
            for (int o = 16; o > 0; o >>= 1) sum += __shfl_xor_sync(0xffffffffu, sum, o);
            if (t < nwin) out[(size_t)b * TT + lo + t] = e / sum;
        }
    }
}

// ---------------------------------------------------------------------------
extern "C" void kernel_launch(void* const* d_in, const int* in_sizes, int n_in,
                              void* d_out, int out_size)
{
    const float* input_enc = (const float*)d_in[0];
    const float* input_dec = (const float*)d_in[1];
    const float* prev_att  = (const float*)d_in[2];
    const float* spkr      = (const float*)d_in[3];
    const int*   lengths   = (const int*)  d_in[4];
    const float* speed     = (const float*)d_in[5];
    const float* W_enc     = (const float*)d_in[6];
    const float* b_enc     = (const float*)d_in[7];
    const float* W_spkr    = (const float*)d_in[8];
    const float* conv_w    = (const float*)d_in[9];
    const float* W_dec     = (const float*)d_in[10];
    const float* W_speed   = (const float*)d_in[11];
    const float* Wp1       = (const float*)d_in[12];
    const float* bp1       = (const float*)d_in[13];
    const float* Wp2       = (const float*)d_in[14];
    const float* bp2       = (const float*)d_in[15];
    const float* W_proj    = (const float*)d_in[16];
    // d_in[17] = b_proj: constant shift, cancels in the masked softmax.

    k_fused<<<GRID, 256>>>(input_enc, input_dec, prev_att, spkr, lengths, speed,
                           W_enc, b_enc, W_spkr, conv_w, W_dec, W_speed,
                           Wp1, bp1, Wp2, bp2, W_proj, (float*)d_out);
}

// round 6
// speedup vs baseline: 1.1474x; 1.0009x over previous
#include <cuda_runtime.h>

// Problem constants
#define NB     32
#define TT     4096
#define ENC_H  512
#define ATT_H  256
#define OUTD   80
#define SPK    64
#define KW     31
#define NWMAX  19
#define GRID   256

// Device scratch (no allocations allowed)
__device__ unsigned bar_cnt = 0;
__device__ unsigned bar_gen = 0;                 // monotonic across replays
__device__ unsigned d_cnt2  = 0;                 // prenet2 producer counter
__device__ float    d_argval[NB][8];
__device__ int      d_argidx[NB][8];
__device__ unsigned d_count[NB];
__device__ float    d_bias0[NB][ATT_H];
__device__ float    d_h[1024][NB];               // prenet layer-1, k-major
__device__ float    d_p2part[16][NB][512];       // prenet layer-2 split-K partials
__device__ float    d_logit_part[NB][NWMAX][8];

// grid-wide sense barrier (all GRID blocks co-resident: 2 blocks/SM)
__device__ __forceinline__ void grid_sync()
{
    __syncthreads();
    if (threadIdx.x == 0) {
        volatile unsigned* vg = &bar_gen;
        unsigned gen = *vg;
        __threadfence();
        if (atomicAdd(&bar_cnt, 1u) == GRID - 1) {
            bar_cnt = 0;
            __threadfence();
            atomicAdd(&bar_gen, 1u);
        } else {
            while (*vg == gen) { __nanosleep(32); }
        }
        __threadfence();
    }
    __syncthreads();
}

union SmemU {
    struct {                                // phase A
        float rv[128]; int ri[128];
        float dec_s[8][145];
        float w_s[144][16];
    } a;
    struct {                                // prenet2 (64-k slice)
        float h_s[64][33];
        float wt[64][36];
    } b;
    struct {                                // window (total < 48KB)
        union {
            float enc_s[NWMAX][516];        // full 512-k window, float4 rows
            float red_s[NWMAX][8][33];      // written only after matvec
        } u;
        float p_s[512];
        float bias_red[8][33];
        float pa_s[NWMAX + 30 + 3];
        float convw_s[32 * KW];
        float bias_s[32], benc_s[32], wproj_s[32];
    } c;
};

__global__ __launch_bounds__(256) void k_fused(
    const float* __restrict__ input_enc,
    const float* __restrict__ input_dec,
    const float* __restrict__ prev_att,
    const float* __restrict__ spkr,
    const int*   __restrict__ lengths,
    const float* __restrict__ speed,
    const float* __restrict__ W_enc,
    const float* __restrict__ b_enc,
    const float* __restrict__ W_spkr,
    const float* __restrict__ conv_w,
    const float* __restrict__ W_dec,
    const float* __restrict__ W_speed,
    const float* __restrict__ Wp1,
    const float* __restrict__ bp1,
    const float* __restrict__ Wp2,
    const float* __restrict__ bp2,
    const float* __restrict__ W_proj,
    float* __restrict__ out)
{
    __shared__ SmemU sm;
    __shared__ int last_s, sh_lo, sh_nwin;
    const int tid = threadIdx.x;
    const int blk = blockIdx.x;
    const int b  = blk >> 3;                // batch for argmax/zero/window
    const int cg = blk & 7;                 // channel group for window

    // ============================ PHASE A ============================
    {
        if (blk == 0 && tid == 0) d_cnt2 = 0u;
        if (cg == 0 && tid == 0) d_count[b] = 0u;

        // zero output chunk (512 floats)
        if (tid < 128) {
            ((float4*)(out + (size_t)b * TT + cg * 512))[tid] =
                make_float4(0.f, 0.f, 0.f, 0.f);
        }

        // argmax partial over chunk [cg*512, cg*512+512), first max wins
        if (tid < 128) {
            const float4* pa4 = (const float4*)(prev_att + (size_t)b * TT + cg * 512);
            float4 v = pa4[tid];
            float bv = v.x; int bi = 0;
            if (v.y > bv) { bv = v.y; bi = 1; }
            if (v.z > bv) { bv = v.z; bi = 2; }
            if (v.w > bv) { bv = v.w; bi = 3; }
            sm.a.rv[tid] = bv;
            sm.a.ri[tid] = cg * 512 + tid * 4 + bi;
        }

        // L2 prefetch slice of W_enc (512KB / 256 blocks)
        float pf = 0.f;
        if (tid < 128) {
            float4 w = __ldcg(&((const float4*)W_enc)[blk * 128 + tid]);
            pf = w.x + w.y + w.z + w.w;
        }
        asm volatile("" :: "f"(pf));

        // prenet1: this block handles channels [c1, c1+16) x batches [b0, b0+8)
        const int c1 = (blk & 63) * 16;
        const int b0 = (blk >> 6) * 8;
        for (int i = tid; i < 8 * 144; i += 256) {
            int bb = i / 144, k = i - bb * 144;
            sm.a.dec_s[bb][k] = (k < OUTD) ? input_dec[(b0 + bb) * OUTD + k]
                                           : spkr[(b0 + bb) * SPK + (k - OUTD)];
        }
        for (int i = tid; i < 144 * 16; i += 256) {
            int k = i >> 4, cc = i & 15;
            sm.a.w_s[k][cc] = Wp1[k * 1024 + c1 + cc];
        }
        __syncthreads();

        // argmax reduce 128 -> 1
        for (int s = 64; s > 0; s >>= 1) {
            if (tid < s) {
                float ov = sm.a.rv[tid + s]; int oi = sm.a.ri[tid + s];
                if (ov > sm.a.rv[tid] || (ov == sm.a.rv[tid] && oi < sm.a.ri[tid])) {
                    sm.a.rv[tid] = ov; sm.a.ri[tid] = oi;
                }
            }
            __syncthreads();
        }
        if (tid == 0) { d_argval[b][cg] = sm.a.rv[0]; d_argidx[b][cg] = sm.a.ri[0]; }

        // prenet1 compute: bb = tid>>5, cc = (tid>>1)&15, ss = tid&1
        {
            const int bb = tid >> 5, cc = (tid >> 1) & 15, ss = tid & 1;
            float acc = 0.f;
            #pragma unroll 8
            for (int k = ss * 72; k < ss * 72 + 72; k++)
                acc = fmaf(sm.a.dec_s[bb][k], sm.a.w_s[k][cc], acc);
            acc += __shfl_xor_sync(0xffffffffu, acc, 1);
            if (ss == 0)
                d_h[c1 + cc][b0 + bb] = fmaxf(acc + bp1[c1 + cc], 0.f);
        }

        // cg==0 block: spkr softsign + speed bias
        if (cg == 0) {
            float sa = 0.f;
            #pragma unroll 8
            for (int k = 0; k < SPK; k++)
                sa = fmaf(spkr[b * SPK + k], W_spkr[k * ATT_H + tid], sa);
            float v = sa / (1.f + fabsf(sa));
            d_bias0[b][tid] = fmaf(speed[b], W_speed[tid], v);
        }
    }

    grid_sync();

    // ============================ PHASE B: prenet2 slice =====================
    {
        const int cb = (blk & 15) * 32;
        const int ks = blk >> 4;
        const int k0 = ks * 64;
        const int bb = tid & 31;
        const int s  = tid >> 5;

        for (int i = tid; i < 32 * 64; i += 256) {
            int kk = i >> 5, b2 = i & 31;
            sm.b.h_s[kk][b2] = d_h[k0 + kk][b2];
        }
        for (int i = tid; i < 64 * 32; i += 256) {
            int kk = i >> 5, sc = i & 31;
            sm.b.wt[kk][sc] = Wp2[(k0 + kk) * 512 + cb + sc];
        }
        __syncthreads();

        float4 acc = make_float4(0.f, 0.f, 0.f, 0.f);
        #pragma unroll 8
        for (int kk = 0; kk < 64; kk++) {
            float hv = sm.b.h_s[kk][bb];
            float4 w = *(const float4*)&sm.b.wt[kk][s * 4];
            acc.x = fmaf(hv, w.x, acc.x);
            acc.y = fmaf(hv, w.y, acc.y);
            acc.z = fmaf(hv, w.z, acc.z);
            acc.w = fmaf(hv, w.w, acc.w);
        }
        *(float4*)&d_p2part[ks][bb][cb + s * 4] = acc;

        __threadfence();
        __syncthreads();
        if (tid == 0) atomicAdd(&d_cnt2, 1u);
    }
    __syncthreads();                        // smem union switch b -> c

    // ============================ PHASE C: window ============================
    {
        const int c0 = cg * 32;

        if (tid == 0) {
            float bv = d_argval[b][0]; int bi = d_argidx[b][0];
            #pragma unroll
            for (int j = 1; j < 8; j++) {
                float v = d_argval[b][j];
                if (v > bv) { bv = v; bi = d_argidx[b][j]; }
            }
            int lo = max(bi - 9, 0);
            int hi = min(bi + 9, lengths[b] - 1);
            sh_lo = lo;
            sh_nwin = hi - lo + 1;
        }
        __syncthreads();
        const int lo   = sh_lo;
        const int nwin = sh_nwin;

        // stage the FULL enc window once: 19 rows x 128 float4
        const float4* enc4 = (const float4*)(input_enc + (size_t)b * TT * ENC_H);
        for (int i = tid; i < NWMAX * 128; i += 256) {
            int t = i >> 7, q = i & 127;
            int row = lo + t; if (row > TT - 1) row = TT - 1;   // clamped, unused t>=nwin
            float4 e = enc4[(size_t)row * (ENC_H / 4) + q];
            *(float4*)&sm.c.u.enc_s[t][q * 4] = e;
        }
        // small staging
        for (int i = tid; i < nwin + 30; i += 256) {
            int p = lo - 15 + i;
            sm.c.pa_s[i] = (p >= 0 && p < TT) ? prev_att[(size_t)b * TT + p] : 0.f;
        }
        for (int i = tid; i < 32 * KW; i += 256) sm.c.convw_s[i] = conv_w[c0 * KW + i];
        if (tid < 32) {
            sm.c.benc_s[tid]  = b_enc[c0 + tid];
            sm.c.wproj_s[tid] = W_proj[c0 + tid];
        }
        __syncthreads();

        // enc matvec: cl = tid&15 -> channels c0+cl, c0+cl+16; kq = tid>>4 (16 splits)
        const int cl  = tid & 15;
        const int kq  = tid >> 4;
        const int ca  = c0 + cl;
        const int cb2 = c0 + cl + 16;

        float acc_a[NWMAX], acc_b[NWMAX];
        #pragma unroll
        for (int t = 0; t < NWMAX; t++) { acc_a[t] = 0.f; acc_b[t] = 0.f; }

        #pragma unroll
        for (int tile = 0; tile < 4; tile++) {
            #pragma unroll
            for (int k4 = 0; k4 < 2; k4++) {
                const int kk = tile * 128 + kq * 8 + k4 * 4;
                float4 wa, wb;
                wa.x = W_enc[(kk + 0) * ATT_H + ca];
                wa.y = W_enc[(kk + 1) * ATT_H + ca];
                wa.z = W_enc[(kk + 2) * ATT_H + ca];
                wa.w = W_enc[(kk + 3) * ATT_H + ca];
                wb.x = W_enc[(kk + 0) * ATT_H + cb2];
                wb.y = W_enc[(kk + 1) * ATT_H + cb2];
                wb.z = W_enc[(kk + 2) * ATT_H + cb2];
                wb.w = W_enc[(kk + 3) * ATT_H + cb2];
                #pragma unroll
                for (int t = 0; t < NWMAX; t++) {
                    float4 e = *(const float4*)&sm.c.u.enc_s[t][kk];
                    acc_a[t] = fmaf(e.x, wa.x, acc_a[t]);
                    acc_a[t] = fmaf(e.y, wa.y, acc_a[t]);
                    acc_a[t] = fmaf(e.z, wa.z, acc_a[t]);
                    acc_a[t] = fmaf(e.w, wa.w, acc_a[t]);
                    acc_b[t] = fmaf(e.x, wb.x, acc_b[t]);
                    acc_b[t] = fmaf(e.y, wb.y, acc_b[t]);
                    acc_b[t] = fmaf(e.z, wb.z, acc_b[t]);
                    acc_b[t] = fmaf(e.w, wb.w, acc_b[t]);
                }
            }
        }

        __syncthreads();                    // all enc_s reads done (red_s aliases it)

        // stash per-warp matvec partials
        const int w = tid >> 5;
        #pragma unroll
        for (int t = 0; t < NWMAX; t++) {
            float va = acc_a[t] + __shfl_xor_sync(0xffffffffu, acc_a[t], 16);
            float vb = acc_b[t] + __shfl_xor_sync(0xffffffffu, acc_b[t], 16);
            if ((tid & 31) < 16) {
                sm.c.u.red_s[t][w][cl]      = va;
                sm.c.u.red_s[t][w][cl + 16] = vb;
            }
        }

        // wait for prenet2 producers (overlapped with matvec; usually done)
        if (tid == 0) {
            volatile unsigned* vc = &d_cnt2;
            while (*vc < GRID) { __nanosleep(32); }
        }
        __syncthreads();
        __threadfence();

        // reconstruct pout = relu(bp2 + sum of 16 split-K partials)
        #pragma unroll
        for (int r = 0; r < 2; r++) {
            int k = tid + r * 256;
            float v = bp2[k];
            #pragma unroll
            for (int j = 0; j < 16; j++) v += __ldcg(&d_p2part[j][b][k]);
            sm.c.p_s[k] = fmaxf(v, 0.f);
        }
        __syncthreads();

        // bias slice: pout @ W_dec[:, c0..c0+32) + bias0
        {
            const int cl2 = tid & 31, kq2 = tid >> 5;
            float acc = 0.f;
            #pragma unroll 8
            for (int j = 0; j < 64; j++) {
                int k = kq2 * 64 + j;
                acc = fmaf(sm.c.p_s[k], W_dec[k * ATT_H + c0 + cl2], acc);
            }
            sm.c.bias_red[kq2][cl2] = acc;
        }
        __syncthreads();
        if (tid < 32) {
            float s = d_bias0[b][c0 + tid];
            #pragma unroll
            for (int q = 0; q < 8; q++) s += sm.c.bias_red[q][tid];
            sm.c.bias_s[tid] = s;
        }
        __syncthreads();

        // parallel tail: warp tq handles t = p*8 + tq
        const int c2 = tid & 31;
        const int tq = tid >> 5;
        #pragma unroll
        for (int p = 0; p < 3; p++) {
            const int t = p * 8 + tq;
            float v = 0.f;
            if (t < nwin) {
                float s = 0.f;
                #pragma unroll
                for (int q = 0; q < 8; q++) s += sm.c.u.red_s[t][q][c2];
                s += sm.c.benc_s[c2];
                s = s / (1.f + fabsf(s));
                s += sm.c.bias_s[c2];
                float cv = 0.f;
                #pragma unroll
                for (int j = 0; j < KW; j++)
                    cv = fmaf(sm.c.pa_s[t + j], sm.c.convw_s[c2 * KW + j], cv);
                s += cv;
                v = tanhf(s) * sm.c.wproj_s[c2];
            }
            #pragma unroll
            for (int o = 16; o > 0; o >>= 1) v += __shfl_down_sync(0xffffffffu, v, o);
            if (c2 == 0 && t < nwin) d_logit_part[b][t][cg] = v;
        }

        // last-block-done fused softmax
        __threadfence();
        __syncthreads();
        if (tid == 0) {
            unsigned old = atomicAdd(&d_count[b], 1u);
            last_s = (old == 7u) ? 1 : 0;
        }
        __syncthreads();
        if (last_s && tid < 32) {
            const int t = tid;
            float lg = -1e30f;
            if (t < nwin) {
                float s = 0.f;
                #pragma unroll
                for (int q = 0; q < 8; q++) s += __ldcg(&d_logit_part[b][t][q]);
                lg = s;
            }
            float m = lg;
            #pragma unroll
            for (int o = 16; o > 0; o >>= 1) m = fmaxf(m, __shfl_xor_sync(0xffffffffu, m, o));
            float e = (t < nwin) ? expf(lg - m) : 0.f;
            float sum = e;
            #pragma unroll
            for (int o = 16; o > 0; o >>= 1) sum += __shfl_xor_sync(0xffffffffu, sum, o);
            if (t < nwin) out[(size_t)b * TT + lo + t] = e / sum;
        }
    }
}

// ---------------------------------------------------------------------------
extern "C" void kernel_launch(void* const* d_in, const int* in_sizes, int n_in,
                              void* d_out, int out_size)
{
    const float* input_enc = (const float*)d_in[0];
    const float* input_dec = (const float*)d_in[1];
    const float* prev_att  = (const float*)d_in[2];
    const float* spkr      = (const float*)d_in[3];
    const int*   lengths   = (const int*)  d_in[4];
    const float* speed     = (const float*)d_in[5];
    const float* W_enc     = (const float*)d_in[6];
    const float* b_enc     = (const float*)d_in[7];
    const float* W_spkr    = (const float*)d_in[8];
    const float* conv_w    = (const float*)d_in[9];
    const float* W_dec     = (const float*)d_in[10];
    const float* W_speed   = (const float*)d_in[11];
    const float* Wp1       = (const float*)d_in[12];
    const float* bp1       = (const float*)d_in[13];
    const float* Wp2       = (const float*)d_in[14];
    const float* bp2       = (const float*)d_in[15];
    const float* W_proj    = (const float*)d_in[16];
    // d_in[17] = b_proj: constant shift, cancels in the masked softmax.

    k_fused<<<GRID, 256>>>(input_enc, input_dec, prev_att, spkr, lengths, speed,
                           W_enc, b_enc, W_spkr, conv_w, W_dec, W_speed,
                           Wp1, bp1, Wp2, bp2, W_proj, (float*)d_out);
}